// round 16
// baseline (speedup 1.0000x reference)
#include <cuda_runtime.h>
#include <math.h>
#include <stdint.h>

#define M_MAX   360448
#define NMAX    8100000
#define PD      614
#define MAXV    1024
#define QFPS    410
#define MAXPTS  32
#define CAP     128
#define LCAP    8192
#define HBINS   2048
#define NB      148
#define NT      256
#define CPT     10      // NB*NT*CPT = 378880 >= M_MAX
#define NSTEPS  (QFPS - 1)
#define NSTEPS1 410
#define SSTRIDE 16      // u64 stride: one slot per 128B line
#define RCOPY   32      // flag replica lines
#define FSTRIDE 16
#define P_CAP   8192    // pool capacity
#define WINB    1024    // histogram window bins
#define DYNSMEM (P_CAP * 20)

__device__ int                g_count[M_MAX];
__device__ int                g_keys[NMAX];
__device__ int                g_newindex[M_MAX];
__device__ unsigned char      g_valid[M_MAX];
__device__ int                g_hist[HBINS];
__device__ int                g_T;
__device__ unsigned int       g_list[LCAP];
__device__ int                g_listn;
__device__ int                g_sel[MAXV];
__device__ int                g_start;
__device__ unsigned long long g_slot[NSTEPS * NB * SSTRIDE];
__device__ unsigned long long g_F0[NSTEPS1 * RCOPY * FSTRIDE];
__device__ unsigned long long g_F1[NSTEPS1 * RCOPY * FSTRIDE];
__device__ unsigned long long g_F2[NSTEPS1 * RCOPY * FSTRIDE];
__device__ int                g_C1[NSTEPS1];
__device__ int                g_C2[NSTEPS1];
__device__ int                g_pooln[NSTEPS1];
__device__ unsigned           g_histR[NSTEPS1 * WINB];
__device__ unsigned           g_pk[P_CAP];
__device__ unsigned           g_pdd[P_CAP];
__device__ float              g_pcx[P_CAP];
__device__ float              g_pcy[P_CAP];
__device__ float              g_pcz[P_CAP];
__device__ int                g_ctr[MAXV];
__device__ int                g_buf[MAXV * CAP];

#define SLOT_N (NSTEPS * NB * SSTRIDE)

struct P9 { float lox, loy, loz, vx, vy, vz; int gx, gy, gz, M; };

__device__ __forceinline__ P9 mkp(const float* vs, const float* cr) {
    P9 p;
    p.lox = cr[0]; p.loy = cr[1]; p.loz = cr[2];
    p.vx = vs[0]; p.vy = vs[1]; p.vz = vs[2];
    p.gx = (int)floorf(__fdiv_rn(__fsub_rn(cr[3], cr[0]), vs[0]));
    p.gy = (int)floorf(__fdiv_rn(__fsub_rn(cr[4], cr[1]), vs[1]));
    p.gz = (int)floorf(__fdiv_rn(__fsub_rn(cr[5], cr[2]), vs[2]));
    p.M = p.gx * p.gy * p.gz;
    return p;
}

// centroid: STRICT separate mul + add (locked — bit-exact vs reference)
__device__ __forceinline__ void decode_centroid(int key, const P9& p,
                                                float& cx, float& cy, float& cz) {
    int gyz = p.gy * p.gz;
    int ix = key / gyz;
    int r  = key - ix * gyz;
    int iy = r / p.gz;
    int iz = r - iy * p.gz;
    cx = __fadd_rn(__fmul_rn((float)ix, p.vx), p.lox);
    cy = __fadd_rn(__fmul_rn((float)iy, p.vy), p.loy);
    cz = __fadd_rn(__fmul_rn((float)iz, p.vz), p.loz);
}

// locked distance formula: fma(dz,dz, fma(dx,dx, rn(dy*dy)))
__device__ __forceinline__ float fps_dist(float ax, float ay, float az,
                                          float bx, float by, float bz) {
    float dx = __fsub_rn(ax, bx);
    float dy = __fsub_rn(ay, by);
    float dz = __fsub_rn(az, bz);
    return __fmaf_rn(dz, dz, __fmaf_rn(dx, dx, __fmul_rn(dy, dy)));
}

__device__ __forceinline__ unsigned long long pack_dk(unsigned d, unsigned k) {
    return ((unsigned long long)d << 32) | (unsigned long long)((k << 1) | 1u);
}

__device__ __forceinline__ unsigned long long pollu64(const unsigned long long* a) {
    const volatile unsigned long long* v = a;
    unsigned long long x = *v;
    while (x == 0ull) x = *v;
    return x;
}

// ---------------- reset ----------------
__global__ void k_reset() {
    int i = blockIdx.x * blockDim.x + threadIdx.x;
    if (i < M_MAX) { g_count[i] = 0; g_newindex[i] = -1; }
    if (i < HBINS) g_hist[i] = 0;
    if (i < LCAP)  g_list[i] = 0xFFFFFFFFu;
    if (i < MAXV)  g_ctr[i] = 0;
    if (i < SLOT_N) g_slot[i] = 0ull;
    if (i < NSTEPS1 * RCOPY * FSTRIDE) { g_F0[i] = 0ull; g_F1[i] = 0ull; g_F2[i] = 0ull; }
    if (i < NSTEPS1 * WINB) g_histR[i] = 0u;
    if (i < NSTEPS1) { g_C1[i] = 0; g_C2[i] = 0; g_pooln[i] = 0; }
    if (i == 0) { g_listn = 0; g_start = 0x7FFFFFFF; g_T = 1; }
}

// ---------------- pass 1: keys + histogram ----------------
__global__ void k_points(const float* __restrict__ pts, const float* vs,
                         const float* cr, int N) {
    int i = blockIdx.x * blockDim.x + threadIdx.x;
    if (i >= N || i >= NMAX) return;
    P9 p = mkp(vs, cr);
    float x = pts[3 * i + 0];
    float y = pts[3 * i + 1];
    float z = pts[3 * i + 2];
    int vxi = (int)floorf(__fdiv_rn(__fsub_rn(x, p.lox), p.vx));
    int vyi = (int)floorf(__fdiv_rn(__fsub_rn(y, p.loy), p.vy));
    int vzi = (int)floorf(__fdiv_rn(__fsub_rn(z, p.loz), p.vz));
    vxi = min(max(vxi, 0), p.gx - 1);
    vyi = min(max(vyi, 0), p.gy - 1);
    vzi = min(max(vzi, 0), p.gz - 1);
    int key = (vxi * p.gy + vyi) * p.gz + vzi;
    g_keys[i] = key;
    atomicAdd(&g_count[key], 1);
}

// ---------------- count histogram ----------------
__global__ void k_hist(const float* vs, const float* cr) {
    int k = blockIdx.x * blockDim.x + threadIdx.x;
    P9 p = mkp(vs, cr);
    if (k >= p.M) return;
    int c = g_count[k];
    if (c > 0) atomicAdd(&g_hist[min(c, HBINS - 1)], 1);
}

// ---------------- threshold T ----------------
__global__ void k_thresh() {
    int t = threadIdx.x;
    int c1 = 2047 - 2 * t;
    int c2 = 2046 - 2 * t;
    int a0 = g_hist[c1];
    int a1 = (c2 >= 0) ? g_hist[c2] : 0;
    int ts = a0 + a1;
    int lane = t & 31, wid = t >> 5;
    int v = ts;
#pragma unroll
    for (int o = 1; o < 32; o <<= 1) {
        int u = __shfl_up_sync(0xFFFFFFFFu, v, o);
        if (lane >= o) v += u;
    }
    __shared__ int wsum[32];
    if (lane == 31) wsum[wid] = v;
    __syncthreads();
    if (wid == 0) {
        int w = wsum[lane];
#pragma unroll
        for (int o = 1; o < 32; o <<= 1) {
            int u = __shfl_up_sync(0xFFFFFFFFu, w, o);
            if (lane >= o) w += u;
        }
        wsum[lane] = w;
    }
    __syncthreads();
    int incl = v + (wid > 0 ? wsum[wid - 1] : 0);
    int E = incl - ts;
    int s1 = E + a0;
    int s2 = E + a0 + a1;
    if (c1 >= 1 && s1 >= PD && E < PD)  g_T = c1;
    if (c2 >= 1 && s2 >= PD && s1 < PD) g_T = c2;
    if (t == 1023 && s1 < PD) g_T = 1;
}

// ---------------- collect ----------------
__global__ void k_collect(const float* vs, const float* cr) {
    int k = blockIdx.x * blockDim.x + threadIdx.x;
    P9 p = mkp(vs, cr);
    if (k >= p.M) return;
    int c = g_count[k];
    if (c >= g_T) {
        int pos = atomicAdd(&g_listn, 1);
        if (pos < LCAP) {
            unsigned cc = (unsigned)min(c, HBINS - 1);
            g_list[pos] = (((unsigned)(HBINS - 1) - cc) << 19) | (unsigned)k;
        }
    }
}

// ---------------- sorttop ----------------
__global__ void k_sorttop() {
    __shared__ unsigned int s[LCAP];
    int tid = threadIdx.x;
    int n = g_listn;
    int len = (n <= 2048) ? 2048 : LCAP;
    for (int t = tid; t < len; t += blockDim.x) s[t] = g_list[t];
    __syncthreads();
    for (int ks = 2; ks <= len; ks <<= 1) {
        for (int j = ks >> 1; j > 0; j >>= 1) {
            for (int t = tid; t < len; t += blockDim.x) {
                int ixj = t ^ j;
                if (ixj > t) {
                    bool up = ((t & ks) == 0);
                    unsigned a = s[t], b = s[ixj];
                    if ((a > b) == up) { s[t] = b; s[ixj] = a; }
                }
            }
            __syncthreads();
        }
    }
    if (tid < PD) {
        int key = (int)(s[tid] & 0x7FFFFu);
        g_sel[tid] = key;
        g_newindex[key] = tid;
    }
}

// ---------------- prep ----------------
__global__ void k_prep(const float* vs, const float* cr) {
    int k = blockIdx.x * blockDim.x + threadIdx.x;
    P9 p = mkp(vs, cr);
    if (k >= p.M) return;
    int v = (g_count[k] > 0 && g_newindex[k] < 0) ? 1 : 0;
    g_valid[k] = (unsigned char)v;
    if (v) atomicMin(&g_start, k);
}

// ---------------- persistent FPS: batched-sync pool algorithm ----------------
extern __shared__ unsigned char dynp[];
__global__ __launch_bounds__(NT) void k_fps(const float* vs, const float* cr) {
    P9 p = mkp(vs, cr);
    int tid = threadIdx.x, b = blockIdx.x;
    int lane = tid & 31, wid = tid >> 5;
    int base = b * (NT * CPT);

    unsigned* s_pk = (unsigned*)dynp;
    unsigned* s_pd = s_pk + P_CAP;
    float* s_cx = (float*)(s_pd + P_CAP);
    float* s_cy = s_cx + P_CAP;
    float* s_cz = s_cy + P_CAP;

    __shared__ unsigned long long swarp[NT / 32];
    __shared__ unsigned hws[NT / 32];
    __shared__ float winx[NSTEPS1], winy[NSTEPS1], winz[NSTEPS1];
    __shared__ int sh_i[8];     // 0:sdone 1:binW 2:brel 3:stop 4:lastk 5:pooln 6:bstar
    __shared__ float sh_w[3];

    float dist[CPT], cx[CPT], cy[CPT], cz[CPT];
    unsigned vm = 0;
    int startk = g_start;
    float sx, sy, sz;
    decode_centroid(startk, p, sx, sy, sz);
#pragma unroll
    for (int j = 0; j < CPT; j++) {
        int k = base + j * NT + tid;
        float X = 0.f, Y = 0.f, Z = 0.f;
        int ok = 0;
        if (k < p.M) {
            ok = g_valid[k];
            decode_centroid(k, p, X, Y, Z);
        }
        cx[j] = X; cy[j] = Y; cz[j] = Z;
        dist[j] = fps_dist(X, Y, Z, sx, sy, sz);  // min(inf, d) == d
        vm |= (ok ? 1u : 0u) << j;
    }
    if (b == 0 && tid == 0) g_sel[PD] = startk;

    int applied = 0;
    int sdone = 0;

    for (int r = 0; r < NSTEPS; r++) {
        if (r > 0 && b != 0) {
            if (tid == 0) {
                unsigned long long v = pollu64(&g_F0[((size_t)r * RCOPY + (b & 31)) * FSTRIDE]);
                sh_i[0] = (int)(v >> 1);
            }
            __syncthreads();
            sdone = sh_i[0];
            if (sdone >= NSTEPS) return;
        }
        // apply pending winners [applied, sdone)
        int delta = sdone - applied;
        if (delta > 0) {
            for (int i = tid; i < delta; i += NT) {
                int key = __ldcg(&g_sel[PD + 1 + applied + i]);
                decode_centroid(key, p, winx[i], winy[i], winz[i]);
            }
            __syncthreads();
            for (int i = 0; i < delta; i++) {
                float lx = winx[i], ly = winy[i], lz = winz[i];
#pragma unroll
                for (int j = 0; j < CPT; j++)
                    dist[j] = fminf(dist[j], fps_dist(cx[j], cy[j], cz[j], lx, ly, lz));
            }
            applied = sdone;
            __syncthreads();
        }
        // block argmax
        unsigned bd = 0u, bk = 0x7FFFFFFFu;
#pragma unroll
        for (int j = 0; j < CPT; j++) {
            if ((vm >> j) & 1u) {
                unsigned db = __float_as_uint(dist[j]);
                if (db > bd) { bd = db; bk = (unsigned)(base + j * NT + tid); }
            }
        }
        {
            unsigned dmax = __reduce_max_sync(0xFFFFFFFFu, bd);
            unsigned kc = (bd == dmax) ? bk : 0x7FFFFFFFu;
            unsigned kmin = __reduce_min_sync(0xFFFFFFFFu, kc);
            if (lane == 0) swarp[wid] = ((unsigned long long)dmax << 32) | kmin;
        }
        __syncthreads();
        if (tid == 0) {
            unsigned pd = 0u, pk = 0x7FFFFFFFu;
#pragma unroll
            for (int w = 0; w < NT / 32; w++) {
                unsigned long long t = swarp[w];
                unsigned d = (unsigned)(t >> 32), k = (unsigned)t;
                if (d > pd || (d == pd && k < pk)) { pd = d; pk = k; }
            }
            *((volatile unsigned long long*)&g_slot[((size_t)r * NB + b) * SSTRIDE]) =
                pack_dk(pd, pk);
        }
        __syncthreads();

        int binW;
        if (b == 0) {
            unsigned d = 0u, k = 0x7FFFFFFFu;
            if (tid < 160) {
                if (tid < NB) {
                    unsigned long long v = pollu64(&g_slot[((size_t)r * NB + tid) * SSTRIDE]);
                    d = (unsigned)(v >> 32);
                    k = ((unsigned)v) >> 1;
                }
                unsigned dmax = __reduce_max_sync(0xFFFFFFFFu, d);
                unsigned kc = (d == dmax) ? k : 0x7FFFFFFFu;
                unsigned kmin = __reduce_min_sync(0xFFFFFFFFu, kc);
                if ((tid & 31) == 0) swarp[tid >> 5] = ((unsigned long long)dmax << 32) | kmin;
            }
            __syncthreads();
            if (tid == 0) {
                unsigned dW = 0u, kW = 0x7FFFFFFFu;
#pragma unroll
                for (int w = 0; w < 5; w++) {
                    unsigned long long t = swarp[w];
                    unsigned dd = (unsigned)(t >> 32), kk = (unsigned)t;
                    if (dd > dW || (dd == dW && kk < kW)) { dW = dd; kW = kk; }
                }
                g_sel[PD + 1 + sdone] = (int)kW;
                int nd = sdone + 1;
                sh_i[0] = nd;
                if (nd >= NSTEPS) {
                    sh_i[3] = 1;
                    __threadfence();
                    for (int c = 0; c < RCOPY; c++)
                        *((volatile unsigned long long*)
                              &g_F1[((size_t)r * RCOPY + c) * FSTRIDE]) = 3ull;
                } else {
                    sh_i[1] = (int)(dW >> 15);
                    sh_i[4] = (int)kW;
                    sh_i[3] = 0;
                    __threadfence();
                    unsigned long long f = (((unsigned long long)(dW >> 15)) << 2) | 1ull;
                    for (int c = 0; c < RCOPY; c++)
                        *((volatile unsigned long long*)
                              &g_F1[((size_t)r * RCOPY + c) * FSTRIDE]) = f;
                }
            }
            __syncthreads();
            sdone = sh_i[0];
            if (sh_i[3]) return;
            binW = sh_i[1];
        } else {
            if (tid == 0) {
                unsigned long long v = pollu64(&g_F1[((size_t)r * RCOPY + (b & 31)) * FSTRIDE]);
                sh_i[3] = (v & 2ull) ? 1 : 0;
                sh_i[1] = (int)(v >> 2);
            }
            __syncthreads();
            if (sh_i[3]) return;
            binW = sh_i[1];
        }

        // windowed histogram of top dist bits
        int lo = binW - (WINB - 1);
#pragma unroll
        for (int j = 0; j < CPT; j++) {
            if ((vm >> j) & 1u) {
                int idx = (int)(__float_as_uint(dist[j]) >> 15) - lo;
                if (idx >= 0 && idx < WINB)
                    atomicAdd(&g_histR[(size_t)r * WINB + idx], 1u);
            }
        }
        __threadfence();
        __syncthreads();
        if (tid == 0) atomicAdd(&g_C1[r], 1);

        if (b == 0) {
            if (tid == 0) {
                volatile int* c = &g_C1[r];
                while (*c < NB) { }
                sh_i[6] = WINB;
            }
            __syncthreads();
            // suffix scan: thread t owns bins [(255-t)*4 .. +3]
            int bb = (255 - tid) * 4;
            unsigned h3 = __ldcg(&g_histR[(size_t)r * WINB + bb + 3]);
            unsigned h2 = __ldcg(&g_histR[(size_t)r * WINB + bb + 2]);
            unsigned h1 = __ldcg(&g_histR[(size_t)r * WINB + bb + 1]);
            unsigned h0 = __ldcg(&g_histR[(size_t)r * WINB + bb + 0]);
            unsigned tot = h0 + h1 + h2 + h3;
            unsigned vsc = tot;
#pragma unroll
            for (int o = 1; o < 32; o <<= 1) {
                unsigned u = __shfl_up_sync(0xFFFFFFFFu, vsc, o);
                if (lane >= o) vsc += u;
            }
            if (lane == 31) hws[wid] = vsc;
            __syncthreads();
            unsigned add = 0;
            for (int w = 0; w < wid; w++) add += hws[w];
            unsigned excl = vsc + add - tot;
            int best = WINB;
            if (excl + tot <= P_CAP) best = bb;
            else if (excl + h3 + h2 + h1 <= P_CAP) best = bb + 1;
            else if (excl + h3 + h2 <= P_CAP) best = bb + 2;
            else if (excl + h3 <= P_CAP) best = bb + 3;
            if (best < WINB) atomicMin(&sh_i[6], best);
            __syncthreads();
            if (tid == 0) {
                int bs = sh_i[6];
                sh_i[2] = bs;
                unsigned long long f = (((unsigned long long)bs) << 2) | 1ull;
                for (int c = 0; c < RCOPY; c++)
                    *((volatile unsigned long long*)
                          &g_F2[((size_t)r * RCOPY + c) * FSTRIDE]) = f;
            }
            __syncthreads();
        } else {
            if (tid == 0) {
                unsigned long long v = pollu64(&g_F2[((size_t)r * RCOPY + (b & 31)) * FSTRIDE]);
                sh_i[2] = (int)(v >> 2);
            }
            __syncthreads();
        }

        unsigned theta = ((unsigned)(lo + sh_i[2])) << 15;
        // extract pool
#pragma unroll
        for (int j = 0; j < CPT; j++) {
            if ((vm >> j) & 1u) {
                unsigned dbj = __float_as_uint(dist[j]);
                if (dbj >= theta) {
                    int pos = atomicAdd(&g_pooln[r], 1);
                    if (pos < P_CAP) {
                        g_pk[pos] = (unsigned)(base + j * NT + tid);
                        g_pdd[pos] = dbj;
                        g_pcx[pos] = cx[j];
                        g_pcy[pos] = cy[j];
                        g_pcz[pos] = cz[j];
                    }
                }
            }
        }
        __threadfence();
        __syncthreads();
        if (tid == 0) atomicAdd(&g_C2[r], 1);
        if (b != 0) continue;

        // ---- block 0: pool phase ----
        if (tid == 0) {
            volatile int* c = &g_C2[r];
            while (*c < NB) { }
            volatile int* pn = &g_pooln[r];
            int n0 = *pn;
            sh_i[5] = (n0 < P_CAP) ? n0 : P_CAP;
        }
        __syncthreads();
        int n = sh_i[5];
        for (int i = tid; i < n; i += NT) {
            s_pk[i] = __ldcg(&g_pk[i]);
            s_pd[i] = __ldcg(&g_pdd[i]);
            s_cx[i] = __ldcg(&g_pcx[i]);
            s_cy[i] = __ldcg(&g_pcy[i]);
            s_cz[i] = __ldcg(&g_pcz[i]);
        }
        __syncthreads();
        int lastk = sh_i[4];
        while (true) {
            if (tid == 0) decode_centroid(lastk, p, sh_w[0], sh_w[1], sh_w[2]);
            __syncthreads();
            float lx = sh_w[0], ly = sh_w[1], lz = sh_w[2];
            unsigned pbd = 0u, pbk = 0xFFFFFFFFu;
            for (int i = tid; i < n; i += NT) {
                float d = fps_dist(s_cx[i], s_cy[i], s_cz[i], lx, ly, lz);
                unsigned ob = s_pd[i];
                float ndf = fminf(__uint_as_float(ob), d);
                unsigned nb = __float_as_uint(ndf);
                s_pd[i] = nb;
                unsigned key = s_pk[i];
                if (nb > pbd || (nb == pbd && key < pbk)) { pbd = nb; pbk = key; }
            }
            unsigned dmax = __reduce_max_sync(0xFFFFFFFFu, pbd);
            unsigned kc = (pbd == dmax) ? pbk : 0xFFFFFFFFu;
            unsigned kmin = __reduce_min_sync(0xFFFFFFFFu, kc);
            if (lane == 0) swarp[wid] = ((unsigned long long)dmax << 32) | kmin;
            __syncthreads();
            if (tid == 0) {
                unsigned pd2 = 0u, pk2 = 0xFFFFFFFFu;
#pragma unroll
                for (int w = 0; w < NT / 32; w++) {
                    unsigned long long t = swarp[w];
                    unsigned dd = (unsigned)(t >> 32), kk = (unsigned)t;
                    if (dd > pd2 || (dd == pd2 && kk < pk2)) { pd2 = dd; pk2 = kk; }
                }
                int cs = sh_i[0];
                if (pd2 >= theta && cs < NSTEPS) {
                    g_sel[PD + 1 + cs] = (int)pk2;
                    sh_i[0] = cs + 1;
                    sh_i[4] = (int)pk2;
                    sh_i[3] = (cs + 1 >= NSTEPS) ? 2 : 0;
                } else {
                    sh_i[3] = 1;
                }
            }
            __syncthreads();
            int st = sh_i[3];
            if (st == 1) break;
            lastk = sh_i[4];
            if (st == 2) {
                if (tid == 0) {
                    __threadfence();
                    unsigned long long f = (((unsigned long long)NSTEPS) << 1) | 1ull;
                    for (int c = 0; c < RCOPY; c++)
                        *((volatile unsigned long long*)
                              &g_F0[((size_t)(r + 1) * RCOPY + c) * FSTRIDE]) = f;
                }
                return;
            }
        }
        sdone = sh_i[0];
        if (tid == 0) {
            __threadfence();
            unsigned long long f = (((unsigned long long)sdone) << 1) | 1ull;
            for (int c = 0; c < RCOPY; c++)
                *((volatile unsigned long long*)
                      &g_F0[((size_t)(r + 1) * RCOPY + c) * FSTRIDE]) = f;
        }
        __syncthreads();
    }
}

// ---------------- finalize ----------------
__global__ void k_final(const float* vs, const float* cr, float* out, int out_size) {
    int j = blockIdx.x * blockDim.x + threadIdx.x;
    if (j >= MAXV) return;
    P9 p = mkp(vs, cr);
    int key = g_sel[j];
    g_newindex[key] = j;
    int gyz = p.gy * p.gz;
    int ix = key / gyz;
    int r  = key - ix * gyz;
    int iy = r / p.gz;
    int iz = r - iy * p.gz;
    int cbase = MAXV * MAXPTS * 3;
    if (out_size >= cbase + MAXV * 3) {
        out[cbase + 3 * j + 0] = (float)ix;
        out[cbase + 3 * j + 1] = (float)iy;
        out[cbase + 3 * j + 2] = (float)iz;
    }
    int nbase = cbase + MAXV * 3;
    if (out_size >= nbase + MAXV)
        out[nbase + j] = (float)min(g_count[key], MAXPTS);
}

// ---------------- pass 2 ----------------
__global__ void k_cpts(int N) {
    int i = blockIdx.x * blockDim.x + threadIdx.x;
    if (i >= N || i >= NMAX) return;
    int k = g_keys[i];
    int s = g_newindex[k];
    if (s >= 0) {
        int pos = atomicAdd(&g_ctr[s], 1);
        if (pos < CAP) g_buf[s * CAP + pos] = i;
    }
}

// ---------------- emit ----------------
__global__ void k_emit(const float* __restrict__ pts, float* out) {
    __shared__ int sb[CAP];
    int s = blockIdx.x, t = threadIdx.x;
    int m = min(g_ctr[s], CAP);
    sb[t] = (t < m) ? g_buf[s * CAP + t] : 0x7FFFFFFF;
    __syncthreads();
    for (int ks = 2; ks <= CAP; ks <<= 1) {
        for (int j = ks >> 1; j > 0; j >>= 1) {
            int ixj = t ^ j;
            if (ixj > t) {
                bool up = ((t & ks) == 0);
                int a = sb[t], c = sb[ixj];
                if ((a > c) == up) { sb[t] = c; sb[ixj] = a; }
            }
            __syncthreads();
        }
    }
    int num = min(m, MAXPTS);
    if (t < num) {
        int idx = sb[t];
        out[(s * MAXPTS + t) * 3 + 0] = pts[3 * idx + 0];
        out[(s * MAXPTS + t) * 3 + 1] = pts[3 * idx + 1];
        out[(s * MAXPTS + t) * 3 + 2] = pts[3 * idx + 2];
    }
}

// ---------------- launch ----------------
extern "C" void kernel_launch(void* const* d_in, const int* in_sizes, int n_in,
                              void* d_out, int out_size) {
    const float* pts = nullptr;
    const float* vs = nullptr;
    const float* cr = nullptr;
    int N = 0;
    for (int i = 0; i < n_in; i++) {
        if (in_sizes[i] == 3) vs = (const float*)d_in[i];
        else if (in_sizes[i] == 6) cr = (const float*)d_in[i];
        else { pts = (const float*)d_in[i]; N = in_sizes[i] / 3; }
    }
    float* out = (float*)d_out;

    cudaFuncSetAttribute(k_fps, cudaFuncAttributeMaxDynamicSharedMemorySize, DYNSMEM);

    cudaMemsetAsync(d_out, 0, (size_t)out_size * sizeof(float), 0);
    int rb = (SLOT_N + 255) / 256;
    k_reset<<<rb, 256>>>();
    k_points<<<(N + 255) / 256, 256>>>(pts, vs, cr, N);
    k_hist<<<(M_MAX + 255) / 256, 256>>>(vs, cr);
    k_thresh<<<1, 1024>>>();
    k_collect<<<(M_MAX + 255) / 256, 256>>>(vs, cr);
    k_sorttop<<<1, 1024>>>();
    k_prep<<<(M_MAX + 255) / 256, 256>>>(vs, cr);
    k_fps<<<NB, NT, DYNSMEM>>>(vs, cr);
    k_final<<<(MAXV + 255) / 256, 256>>>(vs, cr, out, out_size);
    k_cpts<<<(N + 255) / 256, 256>>>(N);
    k_emit<<<MAXV, CAP>>>(pts, out);
}

// round 17
// speedup vs baseline: 1.8719x; 1.8719x over previous
#include <cuda_runtime.h>
#include <math.h>
#include <stdint.h>

#define M_MAX   360448
#define NMAX    8100000
#define PD      614
#define MAXV    1024
#define QFPS    410
#define MAXPTS  32
#define CAP     128
#define LCAP    8192
#define HBINS   2048
#define NB      148     // block 0 = dedicated reducer, 1..147 compute
#define NCB     147
#define NT      256
#define CPT     10      // NCB*NT*CPT = 376320 >= M_MAX
#define NSTEPS  (QFPS - 1)
#define RCOPY   32      // result replicas (separate 128B lines)
#define RSTRIDE 16      // u64 stride between replicas = 128B
#define SLOT_N  (NSTEPS * NCB)
#define RES_N   (NSTEPS * RCOPY * RSTRIDE)

__device__ int                g_count[M_MAX];
__device__ int                g_keys[NMAX];
__device__ int                g_newindex[M_MAX];
__device__ unsigned char      g_valid[M_MAX];
__device__ int                g_hist[HBINS];
__device__ int                g_T;
__device__ unsigned int       g_list[LCAP];
__device__ int                g_listn;
__device__ int                g_sel[MAXV];
__device__ int                g_start;
__device__ unsigned long long g_slot[SLOT_N];   // per-block partials (unpadded, 19 lines/step)
__device__ unsigned long long g_resN[RES_N];    // replicated winners (padded lines)
__device__ int                g_ctr[MAXV];
__device__ int                g_buf[MAXV * CAP];

struct P9 { float lox, loy, loz, vx, vy, vz; int gx, gy, gz, M; };

__device__ __forceinline__ P9 mkp(const float* vs, const float* cr) {
    P9 p;
    p.lox = cr[0]; p.loy = cr[1]; p.loz = cr[2];
    p.vx = vs[0]; p.vy = vs[1]; p.vz = vs[2];
    p.gx = (int)floorf(__fdiv_rn(__fsub_rn(cr[3], cr[0]), vs[0]));
    p.gy = (int)floorf(__fdiv_rn(__fsub_rn(cr[4], cr[1]), vs[1]));
    p.gz = (int)floorf(__fdiv_rn(__fsub_rn(cr[5], cr[2]), vs[2]));
    p.M = p.gx * p.gy * p.gz;
    return p;
}

// centroid: STRICT separate mul + add (locked — bit-exact vs reference)
__device__ __forceinline__ void decode_centroid(int key, const P9& p,
                                                float& cx, float& cy, float& cz) {
    int gyz = p.gy * p.gz;
    int ix = key / gyz;
    int r  = key - ix * gyz;
    int iy = r / p.gz;
    int iz = r - iy * p.gz;
    cx = __fadd_rn(__fmul_rn((float)ix, p.vx), p.lox);
    cy = __fadd_rn(__fmul_rn((float)iy, p.vy), p.loy);
    cz = __fadd_rn(__fmul_rn((float)iz, p.vz), p.loz);
}

// pack (dist_bits, key) -> u64 whose nonzero-ness is the ready flag
__device__ __forceinline__ unsigned long long pack_dk(unsigned d, unsigned k) {
    return ((unsigned long long)d << 32) | (unsigned long long)((k << 1) | 1u);
}

// ---------------- reset ----------------
__global__ void k_reset() {
    int i = blockIdx.x * blockDim.x + threadIdx.x;
    if (i < M_MAX) { g_count[i] = 0; g_newindex[i] = -1; }
    if (i < HBINS) g_hist[i] = 0;
    if (i < LCAP)  g_list[i] = 0xFFFFFFFFu;
    if (i < MAXV)  g_ctr[i] = 0;
    if (i < SLOT_N) g_slot[i] = 0ull;
    if (i < RES_N)  g_resN[i] = 0ull;
    if (i == 0) { g_listn = 0; g_start = 0x7FFFFFFF; g_T = 1; }
}

// ---------------- pass 1: keys + histogram ----------------
__global__ void k_points(const float* __restrict__ pts, const float* vs,
                         const float* cr, int N) {
    int i = blockIdx.x * blockDim.x + threadIdx.x;
    if (i >= N || i >= NMAX) return;
    P9 p = mkp(vs, cr);
    float x = pts[3 * i + 0];
    float y = pts[3 * i + 1];
    float z = pts[3 * i + 2];
    int vxi = (int)floorf(__fdiv_rn(__fsub_rn(x, p.lox), p.vx));
    int vyi = (int)floorf(__fdiv_rn(__fsub_rn(y, p.loy), p.vy));
    int vzi = (int)floorf(__fdiv_rn(__fsub_rn(z, p.loz), p.vz));
    vxi = min(max(vxi, 0), p.gx - 1);
    vyi = min(max(vyi, 0), p.gy - 1);
    vzi = min(max(vzi, 0), p.gz - 1);
    int key = (vxi * p.gy + vyi) * p.gz + vzi;
    g_keys[i] = key;
    atomicAdd(&g_count[key], 1);
}

// ---------------- count histogram ----------------
__global__ void k_hist(const float* vs, const float* cr) {
    int k = blockIdx.x * blockDim.x + threadIdx.x;
    P9 p = mkp(vs, cr);
    if (k >= p.M) return;
    int c = g_count[k];
    if (c > 0) atomicAdd(&g_hist[min(c, HBINS - 1)], 1);
}

// ---------------- threshold T: 614th largest count (parallel suffix scan) ----------------
__global__ void k_thresh() {
    int t = threadIdx.x;
    int c1 = 2047 - 2 * t;
    int c2 = 2046 - 2 * t;
    int a0 = g_hist[c1];
    int a1 = (c2 >= 0) ? g_hist[c2] : 0;
    int ts = a0 + a1;
    int lane = t & 31, wid = t >> 5;
    int v = ts;
#pragma unroll
    for (int o = 1; o < 32; o <<= 1) {
        int u = __shfl_up_sync(0xFFFFFFFFu, v, o);
        if (lane >= o) v += u;
    }
    __shared__ int wsum[32];
    if (lane == 31) wsum[wid] = v;
    __syncthreads();
    if (wid == 0) {
        int w = wsum[lane];
#pragma unroll
        for (int o = 1; o < 32; o <<= 1) {
            int u = __shfl_up_sync(0xFFFFFFFFu, w, o);
            if (lane >= o) w += u;
        }
        wsum[lane] = w;
    }
    __syncthreads();
    int incl = v + (wid > 0 ? wsum[wid - 1] : 0);
    int E = incl - ts;
    int s1 = E + a0;
    int s2 = E + a0 + a1;
    if (c1 >= 1 && s1 >= PD && E < PD)  g_T = c1;
    if (c2 >= 1 && s2 >= PD && s1 < PD) g_T = c2;
    if (t == 1023 && s1 < PD) g_T = 1;
}

// ---------------- collect keys with count >= T ----------------
__global__ void k_collect(const float* vs, const float* cr) {
    int k = blockIdx.x * blockDim.x + threadIdx.x;
    P9 p = mkp(vs, cr);
    if (k >= p.M) return;
    int c = g_count[k];
    if (c >= g_T) {
        int pos = atomicAdd(&g_listn, 1);
        if (pos < LCAP) {
            unsigned cc = (unsigned)min(c, HBINS - 1);
            g_list[pos] = (((unsigned)(HBINS - 1) - cc) << 19) | (unsigned)k;
        }
    }
}

// ---------------- sort candidates (dynamic length), top PD (count desc, key asc) ----------------
__global__ void k_sorttop() {
    __shared__ unsigned int s[LCAP];
    int tid = threadIdx.x;
    int n = g_listn;
    int len = (n <= 2048) ? 2048 : LCAP;
    for (int t = tid; t < len; t += blockDim.x) s[t] = g_list[t];
    __syncthreads();
    for (int ks = 2; ks <= len; ks <<= 1) {
        for (int j = ks >> 1; j > 0; j >>= 1) {
            for (int t = tid; t < len; t += blockDim.x) {
                int ixj = t ^ j;
                if (ixj > t) {
                    bool up = ((t & ks) == 0);
                    unsigned a = s[t], b = s[ixj];
                    if ((a > b) == up) { s[t] = b; s[ixj] = a; }
                }
            }
            __syncthreads();
        }
    }
    if (tid < PD) {
        int key = (int)(s[tid] & 0x7FFFFu);
        g_sel[tid] = key;
        g_newindex[key] = tid;
    }
}

// ---------------- FPS validity mask + start (smallest remaining key) ----------------
__global__ void k_prep(const float* vs, const float* cr) {
    int k = blockIdx.x * blockDim.x + threadIdx.x;
    P9 p = mkp(vs, cr);
    if (k >= p.M) return;
    int v = (g_count[k] > 0 && g_newindex[k] < 0) ? 1 : 0;
    g_valid[k] = (unsigned char)v;
    if (v) atomicMin(&g_start, k);
}

// ---------------- persistent FPS: R10 two-hop + dedicated pre-armed reducer ----------------
__global__ __launch_bounds__(NT) void k_fps(const float* vs, const float* cr) {
    P9 p = mkp(vs, cr);
    int tid = threadIdx.x, b = blockIdx.x;
    int lane = tid & 31, wid = tid >> 5;

    __shared__ unsigned long long swarp[NT / 32];
    __shared__ float s_lx, s_ly, s_lz;

    if (b == 0) {
        // -------- dedicated reducer: pollers armed before partials land --------
        if (tid == 0) g_sel[PD] = g_start;
        for (int s = 0; s < NSTEPS; s++) {
            unsigned d = 0u, k = 0x7FFFFFFFu;
            if (tid < 160) {
                if (tid < NCB) {
                    const volatile unsigned long long* sp = &g_slot[s * NCB + tid];
                    unsigned long long v = *sp;
                    while (v == 0ull) { __nanosleep(40); v = *sp; }
                    d = (unsigned)(v >> 32);
                    k = ((unsigned)v) >> 1;
                }
                unsigned dmax = __reduce_max_sync(0xFFFFFFFFu, d);
                unsigned kc = (d == dmax) ? k : 0x7FFFFFFFu;
                unsigned kmin = __reduce_min_sync(0xFFFFFFFFu, kc);
                if ((tid & 31) == 0)
                    swarp[tid >> 5] = ((unsigned long long)dmax << 32) | kmin;
            }
            __syncthreads();
            if (wid == 0) {
                unsigned dd = 0u, kk = 0x7FFFFFFFu;
                if (lane < 5) {
                    unsigned long long t = swarp[lane];
                    dd = (unsigned)(t >> 32);
                    kk = (unsigned)t;
                }
                unsigned dmax = __reduce_max_sync(0xFFFFFFFFu, dd);
                unsigned kc = (dd == dmax) ? kk : 0x7FFFFFFFu;
                unsigned kmin = __reduce_min_sync(0xFFFFFFFFu, kc);
                // parallel fan-out: 32 replica lines, one store per lane
                *((volatile unsigned long long*)
                      &g_resN[(s * RCOPY + lane) * RSTRIDE]) = pack_dk(dmax, kmin);
                if (lane == 0) g_sel[PD + 1 + s] = (int)kmin;
            }
            __syncthreads();
        }
        return;
    }

    // -------- compute blocks (1..147) --------
    int base = (b - 1) * (NT * CPT);
    float dist[CPT], cx[CPT], cy[CPT], cz[CPT];
    unsigned vm = 0;
#pragma unroll
    for (int j = 0; j < CPT; j++) {
        int k = base + j * NT + tid;
        float X = 0.f, Y = 0.f, Z = 0.f;
        int ok = 0;
        if (k < p.M) {
            ok = g_valid[k];
            decode_centroid(k, p, X, Y, Z);
        }
        cx[j] = X; cy[j] = Y; cz[j] = Z;
        dist[j] = __int_as_float(0x7f800000);  // +inf
        vm |= (ok ? 1u : 0u) << j;
    }

    if (tid == 0) decode_centroid(g_start, p, s_lx, s_ly, s_lz);
    __syncthreads();

    for (int s = 0; s < NSTEPS; s++) {
        float lx = s_lx, ly = s_ly, lz = s_lz;

        unsigned bd = 0u;            // best dist bits (nonneg float: uint cmp == float cmp)
        unsigned bk = 0x7FFFFFFFu;   // best key
#pragma unroll
        for (int j = 0; j < CPT; j++) {
            float dx = __fsub_rn(cx[j], lx);
            float dy = __fsub_rn(cy[j], ly);
            float dz = __fsub_rn(cz[j], lz);
            // locked formula: fma(dz,dz, fma(dx,dx, rn(dy*dy)))
            float d = __fmaf_rn(dz, dz, __fmaf_rn(dx, dx, __fmul_rn(dy, dy)));
            float nd = fminf(dist[j], d);
            dist[j] = nd;
            if ((vm >> j) & 1u) {
                unsigned db = __float_as_uint(nd);
                if (db > bd) { bd = db; bk = (unsigned)(base + j * NT + tid); }
                // strict > : ascending key order => ties keep smallest key
            }
        }
        // warp argmax via REDUX (max dist, then min key among winners)
        unsigned dmax = __reduce_max_sync(0xFFFFFFFFu, bd);
        unsigned kc = (bd == dmax) ? bk : 0x7FFFFFFFu;
        unsigned kmin = __reduce_min_sync(0xFFFFFFFFu, kc);
        if (lane == 0) swarp[wid] = ((unsigned long long)dmax << 32) | kmin;
        __syncthreads();
        // tid0: combine warp partials, publish, poll replica (backoff), decode winner
        if (tid == 0) {
            unsigned pd = 0u, pk = 0x7FFFFFFFu;
#pragma unroll
            for (int w = 0; w < NT / 32; w++) {
                unsigned long long t = swarp[w];
                unsigned d = (unsigned)(t >> 32), k = (unsigned)t;
                if (d > pd || (d == pd && k < pk)) { pd = d; pk = k; }
            }
            *((volatile unsigned long long*)&g_slot[s * NCB + (b - 1)]) = pack_dk(pd, pk);
            const volatile unsigned long long* rp =
                &g_resN[(s * RCOPY + (b & (RCOPY - 1))) * RSTRIDE];
            unsigned long long m = *rp;
            while (m == 0ull) { __nanosleep(40); m = *rp; }
            decode_centroid((int)(((unsigned)m) >> 1), p, s_lx, s_ly, s_lz);
        }
        __syncthreads();
    }
}

// ---------------- finalize slots: new_index, coords, nums ----------------
__global__ void k_final(const float* vs, const float* cr, float* out, int out_size) {
    int j = blockIdx.x * blockDim.x + threadIdx.x;
    if (j >= MAXV) return;
    P9 p = mkp(vs, cr);
    int key = g_sel[j];
    g_newindex[key] = j;
    int gyz = p.gy * p.gz;
    int ix = key / gyz;
    int r  = key - ix * gyz;
    int iy = r / p.gz;
    int iz = r - iy * p.gz;
    int cbase = MAXV * MAXPTS * 3;
    if (out_size >= cbase + MAXV * 3) {
        out[cbase + 3 * j + 0] = (float)ix;
        out[cbase + 3 * j + 1] = (float)iy;
        out[cbase + 3 * j + 2] = (float)iz;
    }
    int nbase = cbase + MAXV * 3;
    if (out_size >= nbase + MAXV)
        out[nbase + j] = (float)min(g_count[key], MAXPTS);
}

// ---------------- pass 2: collect point indices of selected voxels ----------------
__global__ void k_cpts(int N) {
    int i = blockIdx.x * blockDim.x + threadIdx.x;
    if (i >= N || i >= NMAX) return;
    int k = g_keys[i];
    int s = g_newindex[k];
    if (s >= 0) {
        int pos = atomicAdd(&g_ctr[s], 1);
        if (pos < CAP) g_buf[s * CAP + pos] = i;
    }
}

// ---------------- per-slot: sort indices, emit first min(count,32) points ----------------
__global__ void k_emit(const float* __restrict__ pts, float* out) {
    __shared__ int sb[CAP];
    int s = blockIdx.x, t = threadIdx.x;
    int m = min(g_ctr[s], CAP);
    sb[t] = (t < m) ? g_buf[s * CAP + t] : 0x7FFFFFFF;
    __syncthreads();
    for (int ks = 2; ks <= CAP; ks <<= 1) {
        for (int j = ks >> 1; j > 0; j >>= 1) {
            int ixj = t ^ j;
            if (ixj > t) {
                bool up = ((t & ks) == 0);
                int a = sb[t], c = sb[ixj];
                if ((a > c) == up) { sb[t] = c; sb[ixj] = a; }
            }
            __syncthreads();
        }
    }
    int num = min(m, MAXPTS);
    if (t < num) {
        int idx = sb[t];
        out[(s * MAXPTS + t) * 3 + 0] = pts[3 * idx + 0];
        out[(s * MAXPTS + t) * 3 + 1] = pts[3 * idx + 1];
        out[(s * MAXPTS + t) * 3 + 2] = pts[3 * idx + 2];
    }
}

// ---------------- launch ----------------
extern "C" void kernel_launch(void* const* d_in, const int* in_sizes, int n_in,
                              void* d_out, int out_size) {
    const float* pts = nullptr;
    const float* vs = nullptr;
    const float* cr = nullptr;
    int N = 0;
    for (int i = 0; i < n_in; i++) {
        if (in_sizes[i] == 3) vs = (const float*)d_in[i];
        else if (in_sizes[i] == 6) cr = (const float*)d_in[i];
        else { pts = (const float*)d_in[i]; N = in_sizes[i] / 3; }
    }
    float* out = (float*)d_out;

    cudaMemsetAsync(d_out, 0, (size_t)out_size * sizeof(float), 0);
    int rb = (M_MAX + 255) / 256;
    k_reset<<<rb, 256>>>();
    k_points<<<(N + 255) / 256, 256>>>(pts, vs, cr, N);
    k_hist<<<rb, 256>>>(vs, cr);
    k_thresh<<<1, 1024>>>();
    k_collect<<<rb, 256>>>(vs, cr);
    k_sorttop<<<1, 1024>>>();
    k_prep<<<rb, 256>>>(vs, cr);
    k_fps<<<NB, NT>>>(vs, cr);
    k_final<<<(MAXV + 255) / 256, 256>>>(vs, cr, out, out_size);
    k_cpts<<<(N + 255) / 256, 256>>>(N);
    k_emit<<<MAXV, CAP>>>(pts, out);
}